// round 2
// baseline (speedup 1.0000x reference)
#include <cuda_runtime.h>

#define B_  2
#define H_  12
#define S_  2048
#define D_  64
#define BH_ (B_ * H_)
#define SCALE_ 0.125f   // 1/sqrt(64)

// ---------------------------------------------------------------------------
// Kernel 1: QK^T logits with mask epilogue.
// C-tile 128x128, 256 threads, 8x8 per-thread register tile.
// Writes masked logits (pre-softmax) into the attention output region.
// ---------------------------------------------------------------------------
__global__ __launch_bounds__(256, 2)
void qk_kernel(const float* __restrict__ q, const float* __restrict__ k,
               const int* __restrict__ mask, float* __restrict__ attn)
{
    __shared__ float sQ[16][132];   // [d][q-row], pad 132 -> 2-way store conflicts max
    __shared__ float sK[16][132];   // [d][k-row]

    const int bh = blockIdx.z;
    const int b  = bh / H_;
    const int q0 = blockIdx.y * 128;
    const int k0 = blockIdx.x * 128;
    const int t  = threadIdx.x;
    const int tq = t >> 4;          // 0..15 -> q rows  tq*8 .. tq*8+7
    const int tk = t & 15;          // 0..15 -> k cols  tk*8 .. tk*8+7

    const float* Qb = q + ((size_t)bh * S_ + q0) * D_;
    const float* Kb = k + ((size_t)bh * S_ + k0) * D_;

    float acc[8][8];
#pragma unroll
    for (int i = 0; i < 8; i++)
#pragma unroll
        for (int j = 0; j < 8; j++) acc[i][j] = 0.0f;

    for (int d0 = 0; d0 < D_; d0 += 16) {
        // Load 128x16 tiles of Q and K, transposed into smem.
        // 128*16 = 2048 floats = 512 float4; 256 threads x 2.
#pragma unroll
        for (int i = 0; i < 2; i++) {
            int vid = t + i * 256;          // 0..511
            int row = vid >> 2;             // 0..127
            int dd  = (vid & 3) * 4;        // 0,4,8,12
            float4 a = *(const float4*)(Qb + (size_t)row * D_ + d0 + dd);
            sQ[dd + 0][row] = a.x; sQ[dd + 1][row] = a.y;
            sQ[dd + 2][row] = a.z; sQ[dd + 3][row] = a.w;
            float4 c = *(const float4*)(Kb + (size_t)row * D_ + d0 + dd);
            sK[dd + 0][row] = c.x; sK[dd + 1][row] = c.y;
            sK[dd + 2][row] = c.z; sK[dd + 3][row] = c.w;
        }
        __syncthreads();

#pragma unroll
        for (int dd = 0; dd < 16; dd++) {
            float4 a0 = *(const float4*)&sQ[dd][tq * 8];
            float4 a1 = *(const float4*)&sQ[dd][tq * 8 + 4];
            float4 b0 = *(const float4*)&sK[dd][tk * 8];
            float4 b1 = *(const float4*)&sK[dd][tk * 8 + 4];
            float av[8] = {a0.x, a0.y, a0.z, a0.w, a1.x, a1.y, a1.z, a1.w};
            float bv[8] = {b0.x, b0.y, b0.z, b0.w, b1.x, b1.y, b1.z, b1.w};
#pragma unroll
            for (int i = 0; i < 8; i++)
#pragma unroll
                for (int j = 0; j < 8; j++)
                    acc[i][j] = fmaf(av[i], bv[j], acc[i][j]);
        }
        __syncthreads();
    }

    // Epilogue: scale + mask (mask==0 -> 1e-9), write raw masked logits.
#pragma unroll
    for (int i = 0; i < 8; i++) {
        int qq = q0 + tq * 8 + i;
        const int4* mp = (const int4*)(mask + ((size_t)b * S_ + qq) * S_ + k0 + tk * 8);
        float4* ap = (float4*)(attn + ((size_t)bh * S_ + qq) * S_ + k0 + tk * 8);
        int4 m0 = mp[0];
        int4 m1 = mp[1];
        float4 r0, r1;
        r0.x = (m0.x == 0) ? 1e-9f : acc[i][0] * SCALE_;
        r0.y = (m0.y == 0) ? 1e-9f : acc[i][1] * SCALE_;
        r0.z = (m0.z == 0) ? 1e-9f : acc[i][2] * SCALE_;
        r0.w = (m0.w == 0) ? 1e-9f : acc[i][3] * SCALE_;
        r1.x = (m1.x == 0) ? 1e-9f : acc[i][4] * SCALE_;
        r1.y = (m1.y == 0) ? 1e-9f : acc[i][5] * SCALE_;
        r1.z = (m1.z == 0) ? 1e-9f : acc[i][6] * SCALE_;
        r1.w = (m1.w == 0) ? 1e-9f : acc[i][7] * SCALE_;
        ap[0] = r0;
        ap[1] = r1;
    }
}

// ---------------------------------------------------------------------------
// Kernel 2: in-place row softmax over the attention region.
// One block (256 threads) per row of 2048; 8 elements/thread in registers.
// ---------------------------------------------------------------------------
__global__ __launch_bounds__(256)
void softmax_kernel(float* __restrict__ attn)
{
    __shared__ float smax[8];
    __shared__ float ssum[8];

    const size_t row = blockIdx.x;          // bh*S + q
    float* p = attn + row * S_;
    const int t    = threadIdx.x;
    const int wid  = t >> 5;
    const int lane = t & 31;

    float4 v0 = ((const float4*)p)[t];
    float4 v1 = ((const float4*)p)[t + 256];

    float m = fmaxf(fmaxf(fmaxf(v0.x, v0.y), fmaxf(v0.z, v0.w)),
                    fmaxf(fmaxf(v1.x, v1.y), fmaxf(v1.z, v1.w)));
#pragma unroll
    for (int o = 16; o > 0; o >>= 1)
        m = fmaxf(m, __shfl_xor_sync(0xffffffffu, m, o));
    if (lane == 0) smax[wid] = m;
    __syncthreads();
    float mr = smax[0];
#pragma unroll
    for (int i = 1; i < 8; i++) mr = fmaxf(mr, smax[i]);

    float e0x = __expf(v0.x - mr), e0y = __expf(v0.y - mr);
    float e0z = __expf(v0.z - mr), e0w = __expf(v0.w - mr);
    float e1x = __expf(v1.x - mr), e1y = __expf(v1.y - mr);
    float e1z = __expf(v1.z - mr), e1w = __expf(v1.w - mr);

    float s = ((e0x + e0y) + (e0z + e0w)) + ((e1x + e1y) + (e1z + e1w));
#pragma unroll
    for (int o = 16; o > 0; o >>= 1)
        s += __shfl_xor_sync(0xffffffffu, s, o);
    if (lane == 0) ssum[wid] = s;
    __syncthreads();
    float total = ssum[0];
#pragma unroll
    for (int i = 1; i < 8; i++) total += ssum[i];

    float inv = 1.0f / total;
    float4 r0 = make_float4(e0x * inv, e0y * inv, e0z * inv, e0w * inv);
    float4 r1 = make_float4(e1x * inv, e1y * inv, e1z * inv, e1w * inv);
    ((float4*)p)[t]       = r0;
    ((float4*)p)[t + 256] = r1;
}

// ---------------------------------------------------------------------------
// Kernel 3: output = P @ V.
// C-tile 128x64, 128 threads, 8x8 per-thread register tile, k-chunks of 32.
// ---------------------------------------------------------------------------
__global__ __launch_bounds__(128, 4)
void av_kernel(const float* __restrict__ attn, const float* __restrict__ v,
               float* __restrict__ out)
{
    __shared__ float sP[32][132];   // [k][q-row]
    __shared__ float sV[32][64];    // [k][d]

    const int bh = blockIdx.y;
    const int q0 = blockIdx.x * 128;
    const int t  = threadIdx.x;
    const int tq = t >> 3;          // 0..15 -> q rows tq*8..
    const int td = t & 7;           // 0..7  -> d cols td*8..

    const float* Pb = attn + ((size_t)bh * S_ + q0) * S_;
    const float* Vb = v + (size_t)bh * S_ * D_;

    float acc[8][8];
#pragma unroll
    for (int i = 0; i < 8; i++)
#pragma unroll
        for (int j = 0; j < 8; j++) acc[i][j] = 0.0f;

    for (int c0 = 0; c0 < S_; c0 += 32) {
        // Load P tile 128x32 transposed: 1024 float4 / 128 threads = 8 each.
#pragma unroll
        for (int i = 0; i < 8; i++) {
            int vid = t + i * 128;
            int row = vid >> 3;         // 0..127
            int c4  = (vid & 7) * 4;    // 0..28
            float4 a = *(const float4*)(Pb + (size_t)row * S_ + c0 + c4);
            sP[c4 + 0][row] = a.x; sP[c4 + 1][row] = a.y;
            sP[c4 + 2][row] = a.z; sP[c4 + 3][row] = a.w;
        }
        // Load V tile 32x64 natural layout: 512 float4 / 128 threads = 4 each.
#pragma unroll
        for (int i = 0; i < 4; i++) {
            int vid = t + i * 128;
            int row = vid >> 4;         // 0..31
            int c4  = (vid & 15) * 4;   // 0..60
            *(float4*)&sV[row][c4] =
                *(const float4*)(Vb + (size_t)(c0 + row) * D_ + c4);
        }
        __syncthreads();

#pragma unroll
        for (int kk = 0; kk < 32; kk++) {
            float4 a0 = *(const float4*)&sP[kk][tq * 8];
            float4 a1 = *(const float4*)&sP[kk][tq * 8 + 4];
            float4 b0 = *(const float4*)&sV[kk][td * 8];
            float4 b1 = *(const float4*)&sV[kk][td * 8 + 4];
            float av[8] = {a0.x, a0.y, a0.z, a0.w, a1.x, a1.y, a1.z, a1.w};
            float bv[8] = {b0.x, b0.y, b0.z, b0.w, b1.x, b1.y, b1.z, b1.w};
#pragma unroll
            for (int i = 0; i < 8; i++)
#pragma unroll
                for (int j = 0; j < 8; j++)
                    acc[i][j] = fmaf(av[i], bv[j], acc[i][j]);
        }
        __syncthreads();
    }

#pragma unroll
    for (int i = 0; i < 8; i++) {
        int qq = q0 + tq * 8 + i;
        float4* op = (float4*)(out + ((size_t)bh * S_ + qq) * D_ + td * 8);
        op[0] = make_float4(acc[i][0], acc[i][1], acc[i][2], acc[i][3]);
        op[1] = make_float4(acc[i][4], acc[i][5], acc[i][6], acc[i][7]);
    }
}

// ---------------------------------------------------------------------------
// Launch: out buffer = [output (B,H,S,D) | attention (B,H,S,S)]
// ---------------------------------------------------------------------------
extern "C" void kernel_launch(void* const* d_in, const int* in_sizes, int n_in,
                              void* d_out, int out_size)
{
    const float* q    = (const float*)d_in[0];
    const float* k    = (const float*)d_in[1];
    const float* v    = (const float*)d_in[2];
    const int*   mask = (const int*)d_in[3];

    float* out  = (float*)d_out;
    float* attn = out + (size_t)BH_ * S_ * D_;

    dim3 g1(S_ / 128, S_ / 128, BH_);
    qk_kernel<<<g1, 256>>>(q, k, mask, attn);

    softmax_kernel<<<(unsigned)(BH_ * S_), 256>>>(attn);

    dim3 g3(S_ / 128, BH_);
    av_kernel<<<g3, 128>>>(attn, v, out);
}